// round 1
// baseline (speedup 1.0000x reference)
#include <cuda_runtime.h>
#include <math_constants.h>

#define G   8
#define CG  32
#define CH  256
#define HWP 16384      // H*W
#define TPB 128
#define PXT 4          // pixels per thread (float4 along W)

__global__ void __launch_bounds__(TPB, 4)
cgblock_kernel(const float* __restrict__ x,
               const float* __restrict__ soft_w1,
               const float* __restrict__ soft_w2,
               const float* __restrict__ top_w1,
               const float* __restrict__ top_w2,
               const float* __restrict__ rr,
               float* __restrict__ out)
{
    // Folded second-stage weights: [o][0..7] = rs*soft_w2[o][g], [o][8..15] = rt*top_w2[o][g]
    __shared__ __align__(16) float s_wc[CH * 16];
    __shared__ float s_w1[G * CG];
    __shared__ float s_tw1[G * 4];

    const int tid = threadIdx.x;

    // branch mixing softmax (cheap, per-thread)
    float r0 = __ldg(rr), r1 = __ldg(rr + 1);
    float rm = fmaxf(r0, r1);
    float er0 = __expf(r0 - rm), er1 = __expf(r1 - rm);
    float rinv = __frcp_rn(er0 + er1);
    float w_top  = er0 * rinv;   // weight on top-k branch
    float w_soft = er1 * rinv;   // weight on softmax branch

    #pragma unroll 4
    for (int i = tid; i < CH * 16; i += TPB) {
        int o = i >> 4, j = i & 15;
        s_wc[i] = (j < 8) ? (w_soft * __ldg(soft_w2 + o * G + j))
                          : (w_top  * __ldg(top_w2  + o * G + (j - 8)));
    }
    #pragma unroll
    for (int i = tid; i < G * CG; i += TPB) s_w1[i] = __ldg(soft_w1 + i);
    if (tid < G * 4) s_tw1[tid] = __ldg(top_w1 + tid);
    __syncthreads();

    // pixel quad assignment: consecutive threads -> consecutive quads along W (coalesced)
    int q  = blockIdx.x * TPB + tid;
    int p  = q * PXT;
    int b  = p >> 14;            // p / (H*W)
    int sp = p & (HWP - 1);      // spatial index, multiple of 4
    const float* xb = x   + (size_t)b * CH * HWP + sp;
    float*       ob = out + (size_t)b * CH * HWP + sp;

    // per-pixel, per-group branch outputs (registers; group loop fully unrolled)
    float sv0[G], sv1[G], sv2[G], sv3[G];
    float tv0[G], tv1[G], tv2[G], tv3[G];

    #pragma unroll
    for (int g = 0; g < G; g++) {
        const float* xg = xb + g * (CG * HWP);
        float es0 = 0.f, es1 = 0.f, es2 = 0.f, es3 = 0.f;      // exp sums
        float ys0 = 0.f, ys1 = 0.f, ys2 = 0.f, ys3 = 0.f;      // softmax-weighted dots
        float a0 = -CUDART_INF_F, b0 = -CUDART_INF_F, c0 = -CUDART_INF_F, d0 = -CUDART_INF_F;
        float a1 = -CUDART_INF_F, b1 = -CUDART_INF_F, c1 = -CUDART_INF_F, d1 = -CUDART_INF_F;
        float a2 = -CUDART_INF_F, b2 = -CUDART_INF_F, c2 = -CUDART_INF_F, d2 = -CUDART_INF_F;
        float a3 = -CUDART_INF_F, b3 = -CUDART_INF_F, c3 = -CUDART_INF_F, d3 = -CUDART_INF_F;

        #pragma unroll 4
        for (int c = 0; c < CG; c++) {
            float4 v = *(const float4*)(xg + c * HWP);
            float w1 = s_w1[g * CG + c];

            // pixel 0
            {
                float e = __expf(v.x); es0 += e; ys0 = fmaf(v.x * e, w1, ys0);
                float f  = fminf(a0, v.x); a0 = fmaxf(a0, v.x);
                float h  = fminf(b0, f);   b0 = fmaxf(b0, f);
                float i2 = fminf(c0, h);   c0 = fmaxf(c0, h);
                d0 = fmaxf(d0, i2);
            }
            // pixel 1
            {
                float e = __expf(v.y); es1 += e; ys1 = fmaf(v.y * e, w1, ys1);
                float f  = fminf(a1, v.y); a1 = fmaxf(a1, v.y);
                float h  = fminf(b1, f);   b1 = fmaxf(b1, f);
                float i2 = fminf(c1, h);   c1 = fmaxf(c1, h);
                d1 = fmaxf(d1, i2);
            }
            // pixel 2
            {
                float e = __expf(v.z); es2 += e; ys2 = fmaf(v.z * e, w1, ys2);
                float f  = fminf(a2, v.z); a2 = fmaxf(a2, v.z);
                float h  = fminf(b2, f);   b2 = fmaxf(b2, f);
                float i2 = fminf(c2, h);   c2 = fmaxf(c2, h);
                d2 = fmaxf(d2, i2);
            }
            // pixel 3
            {
                float e = __expf(v.w); es3 += e; ys3 = fmaf(v.w * e, w1, ys3);
                float f  = fminf(a3, v.w); a3 = fmaxf(a3, v.w);
                float h  = fminf(b3, f);   b3 = fmaxf(b3, f);
                float i2 = fminf(c3, h);   c3 = fmaxf(c3, h);
                d3 = fmaxf(d3, i2);
            }
        }

        float k0 = s_tw1[g * 4 + 0], k1 = s_tw1[g * 4 + 1];
        float k2 = s_tw1[g * 4 + 2], k3 = s_tw1[g * 4 + 3];

        sv0[g] = __fdividef(ys0, es0);
        sv1[g] = __fdividef(ys1, es1);
        sv2[g] = __fdividef(ys2, es2);
        sv3[g] = __fdividef(ys3, es3);
        tv0[g] = fmaf(a0, k0, fmaf(b0, k1, fmaf(c0, k2, d0 * k3)));
        tv1[g] = fmaf(a1, k0, fmaf(b1, k1, fmaf(c1, k2, d1 * k3)));
        tv2[g] = fmaf(a2, k0, fmaf(b2, k1, fmaf(c2, k2, d2 * k3)));
        tv3[g] = fmaf(a3, k0, fmaf(b3, k1, fmaf(c3, k2, d3 * k3)));
    }

    // Phase 2: out[o] = x[o] + sum_g sv[g]*wc[o][g] + tv[g]*wc[o][8+g]
    #pragma unroll 2
    for (int o = 0; o < CH; o++) {
        float4 xv = *(const float4*)(xb + o * HWP);
        const float4* wc = (const float4*)(s_wc + (o << 4));
        float4 wA = wc[0], wB = wc[1], wC = wc[2], wD = wc[3];
        float wS[8] = {wA.x, wA.y, wA.z, wA.w, wB.x, wB.y, wB.z, wB.w};
        float wT[8] = {wC.x, wC.y, wC.z, wC.w, wD.x, wD.y, wD.z, wD.w};

        float o0 = xv.x, o1 = xv.y, o2 = xv.z, o3 = xv.w;
        #pragma unroll
        for (int g = 0; g < G; g++) {
            o0 = fmaf(sv0[g], wS[g], o0); o0 = fmaf(tv0[g], wT[g], o0);
            o1 = fmaf(sv1[g], wS[g], o1); o1 = fmaf(tv1[g], wT[g], o1);
            o2 = fmaf(sv2[g], wS[g], o2); o2 = fmaf(tv2[g], wT[g], o2);
            o3 = fmaf(sv3[g], wS[g], o3); o3 = fmaf(tv3[g], wT[g], o3);
        }
        float4 ov = make_float4(o0, o1, o2, o3);
        *(float4*)(ob + o * HWP) = ov;
    }
}

extern "C" void kernel_launch(void* const* d_in, const int* in_sizes, int n_in,
                              void* d_out, int out_size) {
    const float* x   = (const float*)d_in[0];
    const float* sw1 = (const float*)d_in[1];
    const float* sw2 = (const float*)d_in[2];
    const float* tw1 = (const float*)d_in[3];
    const float* tw2 = (const float*)d_in[4];
    const float* r   = (const float*)d_in[5];
    float* out = (float*)d_out;

    int pixels = out_size / CH;            // 262144
    int quads  = pixels / PXT;             // 65536
    int blocks = quads / TPB;              // 512

    cgblock_kernel<<<blocks, TPB>>>(x, sw1, sw2, tw1, tw2, r, out);
}